// round 1
// baseline (speedup 1.0000x reference)
#include <cuda_runtime.h>
#include <cuda_fp16.h>
#include <cstdint>

// Problem constants (fixed by the dataset)
#define BB 32      // batch
#define II 2048    // input capsules
#define CC 16      // input atoms (contraction dim)
#define DD 32      // output capsules
#define AA 16      // output atoms
#define OO 512     // DD*AA
#define BO (BB*OO) // 16384

// Scratch (static __device__ arrays: no dynamic allocation)
__device__ __half g_votes[(size_t)II * BB * OO];     // [i][b][o] fp16, 67 MB
__device__ float  g_part[256 * BO];                  // per-block partial preact sums, 16 MB
__device__ float  g_actS[BO];                        // act0, then act0+act1

// ---------------------------------------------------------------------------
// K1: votes[i][b][o] = sum_c x[b,i,c] * W[i,c,o]  (fp32 math, fp16 store)
//     also accumulates per-block partial of S[b,o] = sum_i votes (for iter0)
// grid 256 blocks x 256 threads; each block handles 8 consecutive i.
// thread t -> (bq = t>>5 owns b = bq*4..bq*4+3, og = t&31 owns o = og*16..og*16+15)
// ---------------------------------------------------------------------------
__global__ __launch_bounds__(256) void votes_kernel(const float* __restrict__ x,
                                                    const float* __restrict__ w) {
    __shared__ float sW[CC * OO];   // 32 KB: W[i] tile
    __shared__ float sx[BB * CC];   // 2 KB:  x[:, i, :] tile

    const int t  = threadIdx.x;
    const int bq = t >> 5;
    const int og = t & 31;

    float sacc[4][16];
#pragma unroll
    for (int j = 0; j < 4; j++)
#pragma unroll
        for (int a = 0; a < 16; a++) sacc[j][a] = 0.f;

    for (int ii = 0; ii < 8; ii++) {
        const int i = blockIdx.x * 8 + ii;
        __syncthreads();  // protect sW/sx reuse across iterations

        // load W[i] (8192 floats) cooperatively
        const float4* wsrc = (const float4*)(w + (size_t)i * CC * OO);
        float4* wdst = (float4*)sW;
#pragma unroll
        for (int k = 0; k < 8; k++) wdst[t + 256 * k] = wsrc[t + 256 * k];

        // load x[:, i, :] (512 floats)
        if (t < 128) {
            const int b = t >> 2, p = t & 3;
            ((float4*)sx)[t] = *(const float4*)(x + (size_t)b * II * CC + i * CC + p * 4);
        }
        __syncthreads();

        float acc[4][16];
#pragma unroll
        for (int j = 0; j < 4; j++)
#pragma unroll
            for (int a = 0; a < 16; a++) acc[j][a] = 0.f;

        const float4* sWf4 = (const float4*)sW;
#pragma unroll
        for (int c = 0; c < CC; c++) {
            const int i4 = c * 128 + og * 4;
            float4 w0 = sWf4[i4 + 0], w1 = sWf4[i4 + 1], w2 = sWf4[i4 + 2], w3 = sWf4[i4 + 3];
            float wv[16] = {w0.x, w0.y, w0.z, w0.w, w1.x, w1.y, w1.z, w1.w,
                            w2.x, w2.y, w2.z, w2.w, w3.x, w3.y, w3.z, w3.w};
#pragma unroll
            for (int bb = 0; bb < 4; bb++) {
                const float xv = sx[(bq * 4 + bb) * CC + c];
#pragma unroll
                for (int a = 0; a < 16; a++) acc[bb][a] = fmaf(xv, wv[a], acc[bb][a]);
            }
        }

        // store fp16 votes + accumulate S partials
#pragma unroll
        for (int bb = 0; bb < 4; bb++) {
            const int b = bq * 4 + bb;
            __half2 h[8];
#pragma unroll
            for (int a = 0; a < 8; a++) h[a] = __floats2half2_rn(acc[bb][2 * a], acc[bb][2 * a + 1]);
            uint4* dst = (uint4*)(g_votes + ((size_t)(i * BB + b) * OO + og * 16));
            dst[0] = *(uint4*)&h[0];
            dst[1] = *(uint4*)&h[4];
#pragma unroll
            for (int a = 0; a < 16; a++) sacc[bb][a] += acc[bb][a];
        }
    }

    // deterministic per-block partial write (no atomics)
#pragma unroll
    for (int bb = 0; bb < 4; bb++) {
        const int b = bq * 4 + bb;
#pragma unroll
        for (int a = 0; a < 16; a++)
            g_part[blockIdx.x * BO + b * OO + og * 16 + a] = sacc[bb][a];
    }
}

// ---------------------------------------------------------------------------
// Routing pass (iter1 and iter2):
//   per (b,i): u[d] = sum_a votes[b,i,d,a]*actS[b,d,a];
//   route = softmax_d(u); partial_preact[b,d,a] += route[d]*votes[b,i,d,a]
// grid (128 i-chunks, 2 b-halves) x 512 threads. warp = one b, lane = one d.
// Writes per-chunk partials into g_part rows 0..127 (deterministic reduction).
// ---------------------------------------------------------------------------
__global__ __launch_bounds__(512) void route_kernel(const float* __restrict__ actS) {
    const int w    = threadIdx.x >> 5;
    const int lane = threadIdx.x & 31;
    const int b    = blockIdx.y * 16 + w;
    const int d    = lane;

    float ar[16];
    {
        const float4* ap = (const float4*)(actS + (b * DD + d) * AA);
        float4 a0 = ap[0], a1 = ap[1], a2 = ap[2], a3 = ap[3];
        ar[0]=a0.x; ar[1]=a0.y; ar[2]=a0.z; ar[3]=a0.w;
        ar[4]=a1.x; ar[5]=a1.y; ar[6]=a1.z; ar[7]=a1.w;
        ar[8]=a2.x; ar[9]=a2.y; ar[10]=a2.z; ar[11]=a2.w;
        ar[12]=a3.x; ar[13]=a3.y; ar[14]=a3.z; ar[15]=a3.w;
    }

    float acc[16];
#pragma unroll
    for (int a = 0; a < 16; a++) acc[a] = 0.f;

    const int i0 = blockIdx.x * 16;
    for (int ii = 0; ii < 16; ii++) {
        const int i = i0 + ii;
        const uint4* vp = (const uint4*)(g_votes + ((size_t)(i * BB + b) * OO + d * 16));
        uint4 p0 = vp[0], p1 = vp[1];
        float v[16];
        {
            const __half2* h0 = (const __half2*)&p0;
            const __half2* h1 = (const __half2*)&p1;
#pragma unroll
            for (int j = 0; j < 4; j++) {
                float2 f = __half22float2(h0[j]);
                v[2 * j] = f.x; v[2 * j + 1] = f.y;
                float2 g = __half22float2(h1[j]);
                v[8 + 2 * j] = g.x; v[8 + 2 * j + 1] = g.y;
            }
        }
        float u = 0.f;
#pragma unroll
        for (int a = 0; a < 16; a++) u = fmaf(v[a], ar[a], u);

        // softmax over d (full warp, 32 lanes = 32 d)
        float m = u;
#pragma unroll
        for (int o = 16; o >= 1; o >>= 1) m = fmaxf(m, __shfl_xor_sync(0xffffffffu, m, o));
        float e = __expf(u - m);
        float s = e;
#pragma unroll
        for (int o = 16; o >= 1; o >>= 1) s += __shfl_xor_sync(0xffffffffu, s, o);
        const float r = e / s;

#pragma unroll
        for (int a = 0; a < 16; a++) acc[a] = fmaf(r, v[a], acc[a]);
    }

#pragma unroll
    for (int a = 0; a < 16; a++)
        g_part[blockIdx.x * BO + (b * DD + d) * AA + a] = acc[a];
}

// ---------------------------------------------------------------------------
// Squash stage: deterministic reduce of nrows partials, + bias, squash over A.
// 16384 threads, one per (b,d,a); 16-lane shfl segments reduce the atom norm.
// mode 0: dst = act ; mode 1: dst += act (builds act0+act1)
// ---------------------------------------------------------------------------
__global__ __launch_bounds__(256) void squash_kernel(int nrows, float scale,
                                                     const float* __restrict__ bias,
                                                     float* __restrict__ dst,
                                                     int accumulate) {
    const int idx = blockIdx.x * blockDim.x + threadIdx.x;  // 0..16383
    const int o = idx & (OO - 1);

    float sum = 0.f;
    for (int k = 0; k < nrows; k++) sum += g_part[k * BO + idx];

    float val = fmaf(sum, scale, bias[o]);
    float n2 = val * val;
#pragma unroll
    for (int off = 8; off >= 1; off >>= 1) n2 += __shfl_xor_sync(0xffffffffu, n2, off);
    const float f = sqrtf(n2) / (1.f + n2);
    const float res = val * f;

    if (accumulate) dst[idx] += res;
    else            dst[idx] = res;
}

// ---------------------------------------------------------------------------
extern "C" void kernel_launch(void* const* d_in, const int* in_sizes, int n_in,
                              void* d_out, int out_size) {
    const float* x    = (const float*)d_in[0];
    const float* w    = (const float*)d_in[1];
    const float* bias = (const float*)d_in[2];
    float* out = (float*)d_out;

    float* actS = nullptr;
    cudaGetSymbolAddress((void**)&actS, g_actS);

    // iter0: votes + uniform-route sum
    votes_kernel<<<256, 256>>>(x, w);
    squash_kernel<<<64, 256>>>(256, 1.0f / 32.0f, bias, actS, 0);   // actS = act0

    // iter1: route = softmax(u(act0))
    route_kernel<<<dim3(128, 2), 512>>>(actS);
    squash_kernel<<<64, 256>>>(128, 1.0f, bias, actS, 1);           // actS = act0 + act1

    // iter2: route = softmax(u(act0) + u(act1)) = softmax(u(act0+act1))
    route_kernel<<<dim3(128, 2), 512>>>(actS);
    squash_kernel<<<64, 256>>>(128, 1.0f, bias, out, 0);            // final activation
}

// round 2
// speedup vs baseline: 1.6270x; 1.6270x over previous
#include <cuda_runtime.h>
#include <cuda_fp16.h>
#include <cstdint>

// Problem constants (fixed by the dataset)
#define BB 32      // batch
#define II 2048    // input capsules
#define CC 16      // input atoms (contraction dim)
#define DD 32      // output capsules
#define AA 16      // output atoms
#define OO 512     // DD*AA
#define BO (BB*OO) // 16384
#define GRID_V 148 // one votes block per SM

typedef unsigned long long ull;

// Scratch (static __device__ arrays: no dynamic allocation)
__device__ __half g_votes[(size_t)II * BB * OO];     // [i][b][o] fp16, 67 MB (fits L2)
__device__ float  g_part[256 * BO];                  // partial preact sums, 16 MB
__device__ float  g_actS[BO];                        // act0, then act0+act1

// ---------------- packed f32x2 helpers ----------------
__device__ __forceinline__ ull pack2(float lo, float hi) {
    ull r; asm("mov.b64 %0, {%1,%2};" : "=l"(r) : "f"(lo), "f"(hi)); return r;
}
__device__ __forceinline__ void unpack2(ull v, float& lo, float& hi) {
    asm("mov.b64 {%0,%1}, %2;" : "=f"(lo), "=f"(hi) : "l"(v));
}
__device__ __forceinline__ void fma2(ull& d, ull a, ull b) {
    asm("fma.rn.f32x2 %0, %1, %2, %0;" : "+l"(d) : "l"(a), "l"(b));
}
__device__ __forceinline__ void add2(ull& d, ull a) {
    asm("add.rn.f32x2 %0, %1, %0;" : "+l"(d) : "l"(a));
}

// ---------------- cp.async helpers ----------------
__device__ __forceinline__ void cpa16(void* dst, const void* src) {
    unsigned sdst = (unsigned)__cvta_generic_to_shared(dst);
    asm volatile("cp.async.cg.shared.global [%0], [%1], 16;\n" :: "r"(sdst), "l"(src));
}
#define CP_COMMIT() asm volatile("cp.async.commit_group;\n")
#define CP_WAIT(N)  asm volatile("cp.async.wait_group %0;\n" :: "n"(N))

// smem layout for votes kernel: two 32 KB W buffers + two 2 KB x buffers
#define WBUF_F4 2048                 // float4s per W buffer (32 KB)
#define SMEM_VOTES (2*32768 + 2*2048)

// ---------------------------------------------------------------------------
// K1: votes[i][b][o] = sum_c x[b,i,c] * W[i,c,o]  (f32x2 math, fp16 store)
//     accumulates per-block partial of S[b,o] = sum_i votes (for iter0).
// grid 148 x 256 threads, grid-stride over i (13-14 i per block).
// thread t -> bq = t>>5 (4 b's: bq*4..bq*4+3), og = t&31 (d = og, a = 0..15)
// W tile in smem with XOR-swizzled float4 layout (conflict-free LDS.128).
// cp.async double-buffered so the next W tile streams while computing.
// ---------------------------------------------------------------------------
__global__ __launch_bounds__(256, 1) void votes_kernel(const float* __restrict__ x,
                                                       const float* __restrict__ w) {
    extern __shared__ __align__(16) char smem[];
    float4* swbuf = (float4*)smem;                       // [2][2048] float4
    float*  sxbuf = (float*)(smem + 2 * 32768);          // [2][512] float

    const int t  = threadIdx.x;
    const int bq = t >> 5;
    const int og = t & 31;
    const int bx = blockIdx.x;
    const int n  = (II - bx + GRID_V - 1) / GRID_V;      // iterations for this block
    const int swz = (og >> 1) & 7;

    ull sacc[4][8];
#pragma unroll
    for (int j = 0; j < 4; j++)
#pragma unroll
        for (int k = 0; k < 8; k++) sacc[j][k] = 0ull;

    // prefetch iteration 0
    {
        const int i = bx;
        const float4* wsrc = (const float4*)(w + (size_t)i * CC * OO);
#pragma unroll
        for (int kk = 0; kk < 8; kk++) {
            int g = t + 256 * kk;
            int c = g >> 7, q = g & 127;
            cpa16(&swbuf[c * 128 + (q ^ ((q >> 3) & 7))], wsrc + g);
        }
        if (t < 128) {
            int b = t >> 2, p = t & 3;
            cpa16((float4*)sxbuf + t, (const float4*)(x + ((size_t)b * II + i) * CC) + p);
        }
    }
    CP_COMMIT();

    for (int it = 0; it < n; it++) {
        const int i = bx + it * GRID_V;
        const bool hn = (it + 1) < n;
        if (hn) {
            const int i2 = bx + (it + 1) * GRID_V;
            const int buf = (it + 1) & 1;
            const float4* wsrc = (const float4*)(w + (size_t)i2 * CC * OO);
            float4* wd = swbuf + buf * WBUF_F4;
#pragma unroll
            for (int kk = 0; kk < 8; kk++) {
                int g = t + 256 * kk;
                int c = g >> 7, q = g & 127;
                cpa16(&wd[c * 128 + (q ^ ((q >> 3) & 7))], wsrc + g);
            }
            if (t < 128) {
                int b = t >> 2, p = t & 3;
                cpa16((float4*)(sxbuf + buf * 512) + t,
                      (const float4*)(x + ((size_t)b * II + i2) * CC) + p);
            }
        }
        CP_COMMIT();
        if (hn) { CP_WAIT(1); } else { CP_WAIT(0); }
        __syncthreads();

        const float4* sw4 = swbuf + (it & 1) * WBUF_F4;
        const float*  sxp = sxbuf + (it & 1) * 512;

        ull acc[4][8];
#pragma unroll
        for (int j = 0; j < 4; j++)
#pragma unroll
            for (int k = 0; k < 8; k++) acc[j][k] = 0ull;

#pragma unroll
        for (int c = 0; c < CC; c++) {
            float4 w4[4];
#pragma unroll
            for (int k = 0; k < 4; k++)
                w4[k] = sw4[c * 128 + ((og * 4 + k) ^ swz)];
            ull wv[8];
            wv[0] = pack2(w4[0].x, w4[0].y); wv[1] = pack2(w4[0].z, w4[0].w);
            wv[2] = pack2(w4[1].x, w4[1].y); wv[3] = pack2(w4[1].z, w4[1].w);
            wv[4] = pack2(w4[2].x, w4[2].y); wv[5] = pack2(w4[2].z, w4[2].w);
            wv[6] = pack2(w4[3].x, w4[3].y); wv[7] = pack2(w4[3].z, w4[3].w);
#pragma unroll
            for (int bb = 0; bb < 4; bb++) {
                const float xs = sxp[(bq * 4 + bb) * CC + c];
                const ull xx = pack2(xs, xs);
#pragma unroll
                for (int k = 0; k < 8; k++) fma2(acc[bb][k], xx, wv[k]);
            }
        }

        // store fp16 votes + accumulate iter0 partials
#pragma unroll
        for (int bb = 0; bb < 4; bb++) {
            const int b = bq * 4 + bb;
            __half2 h[8];
#pragma unroll
            for (int k = 0; k < 8; k++) {
                float lo, hi; unpack2(acc[bb][k], lo, hi);
                h[k] = __floats2half2_rn(lo, hi);
                add2(sacc[bb][k], acc[bb][k]);
            }
            uint4* dst = (uint4*)(g_votes + ((size_t)i * BB + b) * OO + og * 16);
            dst[0] = *(uint4*)&h[0];
            dst[1] = *(uint4*)&h[4];
        }
        __syncthreads();   // compute done before this buffer is refilled
    }

    // deterministic per-block partial write (row = blockIdx.x, 148 rows)
#pragma unroll
    for (int bb = 0; bb < 4; bb++) {
        const int b = bq * 4 + bb;
        float* dst = g_part + (size_t)bx * BO + b * OO + og * 16;
#pragma unroll
        for (int k = 0; k < 8; k++) {
            float lo, hi; unpack2(sacc[bb][k], lo, hi);
            dst[2 * k] = lo; dst[2 * k + 1] = hi;
        }
    }
}

// ---------------------------------------------------------------------------
// Routing pass (iter1 and iter2): warp = one b, lane = one d; 2 i's in flight.
// No max-subtraction in softmax (|u| bounded well inside fp32 exp range).
// ---------------------------------------------------------------------------
__global__ __launch_bounds__(512) void route_kernel(const float* __restrict__ actS) {
    const int w    = threadIdx.x >> 5;
    const int lane = threadIdx.x & 31;
    const int b    = blockIdx.y * 16 + w;
    const int d    = lane;

    float ar[16];
    {
        const float4* ap = (const float4*)(actS + (b * DD + d) * AA);
        float4 a0 = ap[0], a1 = ap[1], a2 = ap[2], a3 = ap[3];
        ar[0]=a0.x; ar[1]=a0.y; ar[2]=a0.z; ar[3]=a0.w;
        ar[4]=a1.x; ar[5]=a1.y; ar[6]=a1.z; ar[7]=a1.w;
        ar[8]=a2.x; ar[9]=a2.y; ar[10]=a2.z; ar[11]=a2.w;
        ar[12]=a3.x; ar[13]=a3.y; ar[14]=a3.z; ar[15]=a3.w;
    }

    float acc[16];
#pragma unroll
    for (int a = 0; a < 16; a++) acc[a] = 0.f;

    const int i0 = blockIdx.x * 16;
#pragma unroll 2
    for (int ii = 0; ii < 16; ii += 2) {
        const uint4* vp0 = (const uint4*)(g_votes + ((size_t)(i0 + ii)     * BB + b) * OO + d * 16);
        const uint4* vp1 = (const uint4*)(g_votes + ((size_t)(i0 + ii + 1) * BB + b) * OO + d * 16);
        uint4 p0 = vp0[0], p1 = vp0[1];
        uint4 q0 = vp1[0], q1 = vp1[1];

        float v0[16], v1[16];
        {
            const __half2* h;
            h = (const __half2*)&p0;
#pragma unroll
            for (int j = 0; j < 4; j++) { float2 f = __half22float2(h[j]); v0[2*j] = f.x; v0[2*j+1] = f.y; }
            h = (const __half2*)&p1;
#pragma unroll
            for (int j = 0; j < 4; j++) { float2 f = __half22float2(h[j]); v0[8+2*j] = f.x; v0[8+2*j+1] = f.y; }
            h = (const __half2*)&q0;
#pragma unroll
            for (int j = 0; j < 4; j++) { float2 f = __half22float2(h[j]); v1[2*j] = f.x; v1[2*j+1] = f.y; }
            h = (const __half2*)&q1;
#pragma unroll
            for (int j = 0; j < 4; j++) { float2 f = __half22float2(h[j]); v1[8+2*j] = f.x; v1[8+2*j+1] = f.y; }
        }

        float u0 = 0.f, u1 = 0.f;
#pragma unroll
        for (int a = 0; a < 16; a++) { u0 = fmaf(v0[a], ar[a], u0); u1 = fmaf(v1[a], ar[a], u1); }

        float e0 = __expf(u0), e1 = __expf(u1);
        float s0 = e0, s1 = e1;
#pragma unroll
        for (int o = 16; o >= 1; o >>= 1) {
            s0 += __shfl_xor_sync(0xffffffffu, s0, o);
            s1 += __shfl_xor_sync(0xffffffffu, s1, o);
        }
        const float r0 = __fdividef(e0, s0);
        const float r1 = __fdividef(e1, s1);

#pragma unroll
        for (int a = 0; a < 16; a++) acc[a] = fmaf(r0, v0[a], fmaf(r1, v1[a], acc[a]));
    }

#pragma unroll
    for (int a = 0; a < 16; a++)
        g_part[(size_t)blockIdx.x * BO + (b * DD + d) * AA + a] = acc[a];
}

// ---------------------------------------------------------------------------
// Squash: deterministic reduce of nrows partials (8 independent accumulators),
// + bias, squash over the 16-atom groups via 16-lane shfl segments.
// ---------------------------------------------------------------------------
__global__ __launch_bounds__(128) void squash_kernel(int nrows, float scale,
                                                     const float* __restrict__ bias,
                                                     float* __restrict__ dst,
                                                     int accumulate) {
    const int idx = blockIdx.x * 128 + threadIdx.x;  // 0..16383
    const int o = idx & (OO - 1);

    float s[8];
#pragma unroll
    for (int j = 0; j < 8; j++) s[j] = 0.f;
    int k = 0;
    for (; k + 8 <= nrows; k += 8) {
#pragma unroll
        for (int j = 0; j < 8; j++) s[j] += g_part[(size_t)(k + j) * BO + idx];
    }
    for (; k < nrows; k++) s[0] += g_part[(size_t)k * BO + idx];
    float sum = ((s[0] + s[1]) + (s[2] + s[3])) + ((s[4] + s[5]) + (s[6] + s[7]));

    float val = fmaf(sum, scale, bias[o]);
    float n2 = val * val;
#pragma unroll
    for (int off = 8; off >= 1; off >>= 1) n2 += __shfl_xor_sync(0xffffffffu, n2, off);
    const float f = sqrtf(n2) / (1.f + n2);
    const float res = val * f;

    if (accumulate) dst[idx] += res;
    else            dst[idx] = res;
}

// ---------------------------------------------------------------------------
extern "C" void kernel_launch(void* const* d_in, const int* in_sizes, int n_in,
                              void* d_out, int out_size) {
    const float* x    = (const float*)d_in[0];
    const float* w    = (const float*)d_in[1];
    const float* bias = (const float*)d_in[2];
    float* out = (float*)d_out;

    float* actS = nullptr;
    cudaGetSymbolAddress((void**)&actS, g_actS);
    cudaFuncSetAttribute(votes_kernel, cudaFuncAttributeMaxDynamicSharedMemorySize, SMEM_VOTES);

    // iter0: votes + uniform-route sum (partials over 148 blocks)
    votes_kernel<<<GRID_V, 256, SMEM_VOTES>>>(x, w);
    squash_kernel<<<128, 128>>>(GRID_V, 1.0f / 32.0f, bias, actS, 0);   // actS = act0

    // iter1: route = softmax(u(act0))
    route_kernel<<<dim3(128, 2), 512>>>(actS);
    squash_kernel<<<128, 128>>>(128, 1.0f, bias, actS, 1);              // actS = act0 + act1

    // iter2: route = softmax(u(act0) + u(act1)) = softmax(u(act0+act1))
    route_kernel<<<dim3(128, 2), 512>>>(actS);
    squash_kernel<<<128, 128>>>(128, 1.0f, bias, out, 0);               // final activation
}

// round 3
// speedup vs baseline: 1.7808x; 1.0945x over previous
#include <cuda_runtime.h>
#include <cuda_fp16.h>
#include <cstdint>

// Problem constants (fixed by the dataset)
#define BB 32      // batch
#define II 2048    // input capsules
#define CC 16      // input atoms (contraction dim)
#define DD 32      // output capsules
#define AA 16      // output atoms
#define OO 512     // DD*AA
#define BO (BB*OO) // 16384
#define GRID_V 148 // one votes block per SM

typedef unsigned long long ull;

// Scratch (static __device__ arrays: no dynamic allocation)
__device__ __half g_votes[(size_t)II * BB * OO];     // [i][b][o] fp16, 67 MB (L2-resident)
__device__ float  g_part[256 * BO];                  // partial preact sums, 16 MB
__device__ float  g_actS[BO];                        // act0, then act0+act1

// ---------------- packed f32x2 helpers ----------------
__device__ __forceinline__ ull pack2(float lo, float hi) {
    ull r; asm("mov.b64 %0, {%1,%2};" : "=l"(r) : "f"(lo), "f"(hi)); return r;
}
__device__ __forceinline__ void unpack2(ull v, float& lo, float& hi) {
    asm("mov.b64 {%0,%1}, %2;" : "=f"(lo), "=f"(hi) : "l"(v));
}
__device__ __forceinline__ void fma2(ull& d, ull a, ull b) {
    asm("fma.rn.f32x2 %0, %1, %2, %0;" : "+l"(d) : "l"(a), "l"(b));
}
__device__ __forceinline__ void add2(ull& d, ull a) {
    asm("add.rn.f32x2 %0, %1, %0;" : "+l"(d) : "l"(a));
}

// ---------------- cp.async helpers ----------------
__device__ __forceinline__ void cpa16(void* dst, const void* src) {
    unsigned sdst = (unsigned)__cvta_generic_to_shared(dst);
    asm volatile("cp.async.cg.shared.global [%0], [%1], 16;\n" :: "r"(sdst), "l"(src));
}
#define CP_COMMIT() asm volatile("cp.async.commit_group;\n")
#define CP_WAIT(N)  asm volatile("cp.async.wait_group %0;\n" :: "n"(N))

// smem: two 32 KB W buffers + two 2 KB x buffers
#define WBUF_F4 2048
#define SMEM_VOTES (2*32768 + 2*2048)

// swizzle on float4 index within a 128-float4 row: pairwise-swap keeps every
// 8-lane LDS phase on 8 distinct bank-quads (enumerated conflict-free).
__device__ __forceinline__ int swz(int q) { return q ^ ((q >> 3) & 1); }

// ---------------------------------------------------------------------------
// K1: votes[i][b][o] = sum_c x[b,i,c] * W[i,c,o]  (f32x2 math, fp16 store)
// 256 threads: warp w -> half=(w>>2) owns o in [half*256, half*256+256),
//              bg=(w&3) owns b in [bg*8, bg*8+8); lane owns 8 consecutive o.
// 8b x 8o register tile: 32 B of W per thread per c -> LDS 64 B/cyc (half the
// crossbar), FMA-bound at ~14 us chip-wide. cp.async double-buffered.
// ---------------------------------------------------------------------------
__global__ __launch_bounds__(256, 1) void votes_kernel(const float* __restrict__ x,
                                                       const float* __restrict__ w) {
    extern __shared__ __align__(16) char smem[];
    float4* swbuf = (float4*)smem;                       // [2][2048] float4
    float*  sxbuf = (float*)(smem + 2 * 32768);          // [2][512] float

    const int t    = threadIdx.x;
    const int lane = t & 31;
    const int wid  = t >> 5;
    const int half = wid >> 2;          // o-half
    const int bg   = wid & 3;           // b-group
    const int bx   = blockIdx.x;
    const int n    = (II - bx + GRID_V - 1) / GRID_V;

    const int q0   = half * 64 + lane * 2;
    const int idx0 = swz(q0);
    const int idx1 = idx0 ^ 1;

    ull sacc[8][4];
#pragma unroll
    for (int j = 0; j < 8; j++)
#pragma unroll
        for (int k = 0; k < 4; k++) sacc[j][k] = 0ull;

    // prefetch iteration 0
    {
        const float4* wsrc = (const float4*)(w + (size_t)bx * CC * OO);
#pragma unroll
        for (int kk = 0; kk < 8; kk++) {
            int g = t + 256 * kk;
            int c = g >> 7, q = g & 127;
            cpa16(&swbuf[c * 128 + swz(q)], wsrc + g);
        }
        if (t < 128) {
            int b = t >> 2, p = t & 3;
            cpa16((float4*)sxbuf + t, (const float4*)(x + ((size_t)b * II + bx) * CC) + p);
        }
    }
    CP_COMMIT();

    for (int it = 0; it < n; it++) {
        const int i = bx + it * GRID_V;
        const bool hn = (it + 1) < n;
        if (hn) {
            const int i2 = bx + (it + 1) * GRID_V;
            const int buf = (it + 1) & 1;
            const float4* wsrc = (const float4*)(w + (size_t)i2 * CC * OO);
            float4* wd = swbuf + buf * WBUF_F4;
#pragma unroll
            for (int kk = 0; kk < 8; kk++) {
                int g = t + 256 * kk;
                int c = g >> 7, q = g & 127;
                cpa16(&wd[c * 128 + swz(q)], wsrc + g);
            }
            if (t < 128) {
                int b = t >> 2, p = t & 3;
                cpa16((float4*)(sxbuf + buf * 512) + t,
                      (const float4*)(x + ((size_t)b * II + i2) * CC) + p);
            }
        }
        CP_COMMIT();
        if (hn) { CP_WAIT(1); } else { CP_WAIT(0); }
        __syncthreads();

        const float4* sw4 = swbuf + (it & 1) * WBUF_F4;
        const float*  sxp = sxbuf + (it & 1) * 512;

        ull acc[8][4];
#pragma unroll
        for (int j = 0; j < 8; j++)
#pragma unroll
            for (int k = 0; k < 4; k++) acc[j][k] = 0ull;

#pragma unroll
        for (int c = 0; c < CC; c++) {
            const float4 wa = sw4[c * 128 + idx0];
            const float4 wb = sw4[c * 128 + idx1];
            ull wv[4];
            wv[0] = pack2(wa.x, wa.y); wv[1] = pack2(wa.z, wa.w);
            wv[2] = pack2(wb.x, wb.y); wv[3] = pack2(wb.z, wb.w);
#pragma unroll
            for (int bb = 0; bb < 8; bb++) {
                const float xs = sxp[(bg * 8 + bb) * CC + c];   // warp-uniform broadcast
                const ull xx = pack2(xs, xs);
#pragma unroll
                for (int k = 0; k < 4; k++) fma2(acc[bb][k], xx, wv[k]);
            }
        }

        // store fp16 votes (one 16B store per b) + accumulate iter0 partials
        const int obase = half * 256 + lane * 8;
#pragma unroll
        for (int bb = 0; bb < 8; bb++) {
            const int b = bg * 8 + bb;
            __half2 h[4];
#pragma unroll
            for (int k = 0; k < 4; k++) {
                float lo, hi; unpack2(acc[bb][k], lo, hi);
                h[k] = __floats2half2_rn(lo, hi);
                add2(sacc[bb][k], acc[bb][k]);
            }
            *(uint4*)(g_votes + ((size_t)i * BB + b) * OO + obase) = *(uint4*)h;
        }
        __syncthreads();   // compute done before this buffer is refilled
    }

    // deterministic per-block partial write (row = blockIdx.x, 148 rows)
    const int obase = half * 256 + lane * 8;
#pragma unroll
    for (int bb = 0; bb < 8; bb++) {
        const int b = bg * 8 + bb;
        float* dst = g_part + (size_t)bx * BO + b * OO + obase;
#pragma unroll
        for (int k = 0; k < 4; k++) {
            float lo, hi; unpack2(sacc[bb][k], lo, hi);
            dst[2 * k] = lo; dst[2 * k + 1] = hi;
        }
    }
}

// ---------------------------------------------------------------------------
// Routing pass (iter1 and iter2): warp = one b, lane = one d.
// 4 i's of loads issued up front (8x LDG.128 in flight) before the
// convert/dot/softmax chains; votes are L2-resident.
// ---------------------------------------------------------------------------
__global__ __launch_bounds__(512) void route_kernel(const float* __restrict__ actS) {
    const int w    = threadIdx.x >> 5;
    const int lane = threadIdx.x & 31;
    const int b    = blockIdx.y * 16 + w;
    const int d    = lane;

    float ar[16];
    {
        const float4* ap = (const float4*)(actS + (b * DD + d) * AA);
        float4 a0 = ap[0], a1 = ap[1], a2 = ap[2], a3 = ap[3];
        ar[0]=a0.x; ar[1]=a0.y; ar[2]=a0.z; ar[3]=a0.w;
        ar[4]=a1.x; ar[5]=a1.y; ar[6]=a1.z; ar[7]=a1.w;
        ar[8]=a2.x; ar[9]=a2.y; ar[10]=a2.z; ar[11]=a2.w;
        ar[12]=a3.x; ar[13]=a3.y; ar[14]=a3.z; ar[15]=a3.w;
    }

    float acc[16];
#pragma unroll
    for (int a = 0; a < 16; a++) acc[a] = 0.f;

    const int i0 = blockIdx.x * 16;
    for (int ii = 0; ii < 16; ii += 4) {
        uint4 P[8];
#pragma unroll
        for (int j = 0; j < 4; j++) {
            const uint4* vp = (const uint4*)(g_votes + ((size_t)(i0 + ii + j) * BB + b) * OO + d * 16);
            P[2 * j]     = vp[0];
            P[2 * j + 1] = vp[1];
        }
#pragma unroll
        for (int j = 0; j < 4; j++) {
            float v[16];
            {
                const __half2* h0 = (const __half2*)&P[2 * j];
                const __half2* h1 = (const __half2*)&P[2 * j + 1];
#pragma unroll
                for (int q = 0; q < 4; q++) {
                    float2 f = __half22float2(h0[q]); v[2*q]   = f.x; v[2*q+1]   = f.y;
                    float2 g = __half22float2(h1[q]); v[8+2*q] = g.x; v[8+2*q+1] = g.y;
                }
            }
            float u = 0.f;
#pragma unroll
            for (int a = 0; a < 16; a++) u = fmaf(v[a], ar[a], u);

            // softmax over d (32 lanes); |u| small enough to skip max-subtract
            float e = __expf(u);
            float s = e;
#pragma unroll
            for (int o = 16; o >= 1; o >>= 1) s += __shfl_xor_sync(0xffffffffu, s, o);
            const float r = __fdividef(e, s);
#pragma unroll
            for (int a = 0; a < 16; a++) acc[a] = fmaf(r, v[a], acc[a]);
        }
    }

#pragma unroll
    for (int a = 0; a < 16; a++)
        g_part[(size_t)blockIdx.x * BO + (b * DD + d) * AA + a] = acc[a];
}

// ---------------------------------------------------------------------------
// Squash: 1024-thread blocks, 8 reducer threads per output element.
// thread = (ol 0..127, ks 0..7): sums rows ks, ks+8, ... ; smem tree; squash.
// Fixed summation order -> deterministic across graph replays.
// ---------------------------------------------------------------------------
__global__ __launch_bounds__(1024) void squash_kernel(int nrows, float scale,
                                                      const float* __restrict__ bias,
                                                      float* __restrict__ dst,
                                                      int accumulate) {
    __shared__ float red[1024];
    const int ol  = threadIdx.x & 127;
    const int ks  = threadIdx.x >> 7;
    const int idx = blockIdx.x * 128 + ol;     // 0..16383

    float s0 = 0.f, s1 = 0.f;
    int k = ks;
    for (; k + 8 < nrows; k += 16) {
        s0 += g_part[(size_t)k * BO + idx];
        s1 += g_part[(size_t)(k + 8) * BO + idx];
    }
    if (k < nrows) s0 += g_part[(size_t)k * BO + idx];
    red[ks * 128 + ol] = s0 + s1;
    __syncthreads();

    if (threadIdx.x < 128) {
        float sum = ((red[ol] + red[128 + ol]) + (red[256 + ol] + red[384 + ol]))
                  + ((red[512 + ol] + red[640 + ol]) + (red[768 + ol] + red[896 + ol]));
        float val = fmaf(sum, scale, bias[idx & (OO - 1)]);
        float n2 = val * val;
#pragma unroll
        for (int off = 8; off >= 1; off >>= 1)
            n2 += __shfl_xor_sync(0xffffffffu, n2, off);
        const float f = sqrtf(n2) / (1.f + n2);
        const float res = val * f;
        if (accumulate) dst[idx] += res;
        else            dst[idx] = res;
    }
}

// ---------------------------------------------------------------------------
extern "C" void kernel_launch(void* const* d_in, const int* in_sizes, int n_in,
                              void* d_out, int out_size) {
    const float* x    = (const float*)d_in[0];
    const float* w    = (const float*)d_in[1];
    const float* bias = (const float*)d_in[2];
    float* out = (float*)d_out;

    float* actS = nullptr;
    cudaGetSymbolAddress((void**)&actS, g_actS);
    cudaFuncSetAttribute(votes_kernel, cudaFuncAttributeMaxDynamicSharedMemorySize, SMEM_VOTES);

    // iter0: votes + uniform-route sum (partials over 148 blocks)
    votes_kernel<<<GRID_V, 256, SMEM_VOTES>>>(x, w);
    squash_kernel<<<128, 1024>>>(GRID_V, 1.0f / 32.0f, bias, actS, 0);  // actS = act0

    // iter1: route = softmax(u(act0))
    route_kernel<<<dim3(128, 2), 512>>>(actS);
    squash_kernel<<<128, 1024>>>(128, 1.0f, bias, actS, 1);             // actS = act0 + act1

    // iter2: route = softmax(u(act0) + u(act1)) = softmax(u(act0+act1))
    route_kernel<<<dim3(128, 2), 512>>>(actS);
    squash_kernel<<<128, 1024>>>(128, 1.0f, bias, out, 0);              // final activation
}

// round 4
// speedup vs baseline: 2.2100x; 1.2410x over previous
#include <cuda_runtime.h>
#include <cuda_fp16.h>
#include <cstdint>

// Problem constants (fixed by the dataset)
#define BB 32      // batch
#define II 2048    // input capsules
#define CC 16      // input atoms (contraction dim)
#define DD 32      // output capsules
#define AA 16      // output atoms
#define OO 512     // DD*AA
#define BO (BB*OO) // 16384
#define NB 148     // persistent blocks = one per SM (GB300 has 152, all co-resident)
#define NT 512

typedef unsigned long long ull;

// Scratch (static __device__ arrays: no dynamic allocation)
__device__ __half g_votes[(size_t)II * BB * OO];     // [i][b][o] fp16, 67 MB (L2-resident)
__device__ float  g_part[(size_t)NB * BO];           // per-block partials, 9.7 MB
__device__ float  g_actS[BO];                        // act0, then act0+act1
__device__ unsigned g_count;                          // barrier arrive counter (self-resetting)
__device__ volatile unsigned g_sense;                 // barrier generation (monotonic)

// ---------------- packed f32x2 helpers ----------------
__device__ __forceinline__ ull pack2(float lo, float hi) {
    ull r; asm("mov.b64 %0, {%1,%2};" : "=l"(r) : "f"(lo), "f"(hi)); return r;
}
__device__ __forceinline__ void unpack2(ull v, float& lo, float& hi) {
    asm("mov.b64 {%0,%1}, %2;" : "=f"(lo), "=f"(hi) : "l"(v));
}
__device__ __forceinline__ void fma2(ull& d, ull a, ull b) {
    asm("fma.rn.f32x2 %0, %1, %2, %0;" : "+l"(d) : "l"(a), "l"(b));
}
__device__ __forceinline__ void add2(ull& d, ull a) {
    asm("add.rn.f32x2 %0, %1, %0;" : "+l"(d) : "l"(a));
}

// ---------------- cp.async helpers ----------------
__device__ __forceinline__ void cpa16(void* dst, const void* src) {
    unsigned sdst = (unsigned)__cvta_generic_to_shared(dst);
    asm volatile("cp.async.cg.shared.global [%0], [%1], 16;\n" :: "r"(sdst), "l"(src));
}
#define CP_COMMIT() asm volatile("cp.async.commit_group;\n")
#define CP_WAIT(N)  asm volatile("cp.async.wait_group %0;\n" :: "n"(N))

#define WBUF_F4 2048                       // float4s per W buffer (32 KB)
#define SMEM_TOTAL (2*32768 + 2*2048)      // 2 W buffers + 2 x buffers = 69632 B

// swizzle on float4 index within a 128-float4 row (enumerated conflict-free)
__device__ __forceinline__ int swz(int q) { return q ^ ((q >> 3) & 1); }

// ---------------------------------------------------------------------------
// Software grid barrier (sense-reversing). All NB blocks are co-resident
// (1 block/SM), so spinning is deadlock-free. Deterministic: pure sync.
// g_sense is monotonic across graph replays; g_count self-resets to 0.
// ---------------------------------------------------------------------------
__device__ __forceinline__ void grid_sync() {
    __syncthreads();
    if (threadIdx.x == 0) {
        unsigned gen = g_sense;
        __threadfence();
        if (atomicAdd(&g_count, 1u) == NB - 1) {
            g_count = 0;
            __threadfence();
            g_sense = gen + 1;
        } else {
            while (g_sense == gen) __nanosleep(64);
        }
        __threadfence();
    }
    __syncthreads();
}

// ---------------------------------------------------------------------------
// Squash phase: blocks 0..31 (b = blockIdx.x), thread = o in [0,512).
// Fixed-order reduce of NB partial rows, + bias, squash over 16-atom groups.
// ---------------------------------------------------------------------------
__device__ __forceinline__ void squash_phase(float scale, const float* __restrict__ bias,
                                             float* __restrict__ dst, int accumulate) {
    if (blockIdx.x >= BB) return;
    const int b = blockIdx.x, o = threadIdx.x;
    const int idx = b * OO + o;

    float s[4] = {0.f, 0.f, 0.f, 0.f};
    int k = 0;
    for (; k + 4 <= NB; k += 4) {
#pragma unroll
        for (int j = 0; j < 4; j++) s[j] += g_part[(size_t)(k + j) * BO + idx];
    }
    for (; k < NB; k++) s[0] += g_part[(size_t)k * BO + idx];
    float sum = (s[0] + s[1]) + (s[2] + s[3]);

    float val = fmaf(sum, scale, bias[o]);
    float n2 = val * val;
#pragma unroll
    for (int off = 8; off >= 1; off >>= 1)
        n2 += __shfl_xor_sync(0xffffffffu, n2, off);
    const float f = sqrtf(n2) / (1.f + n2);
    const float res = val * f;
    if (accumulate) dst[idx] += res;
    else            dst[idx] = res;
}

// ---------------------------------------------------------------------------
// Route phase: block bx owns contiguous i-range [ilo, ihi). warp = one b
// (two sequential halves b=w, b=w+16); lane = one d. 2 i's interleaved so the
// two softmax shfl chains pipeline. Writes partial preact row bx.
// ---------------------------------------------------------------------------
__device__ __forceinline__ void route_phase() {
    const int wid  = threadIdx.x >> 5;
    const int lane = threadIdx.x & 31;
    const int bx   = blockIdx.x;
    const int ilo  = (bx * II) / NB;
    const int ihi  = ((bx + 1) * II) / NB;
    const int d    = lane;

#pragma unroll 1
    for (int bh = 0; bh < 2; bh++) {
        const int b = wid + bh * 16;

        float ar[16];
        {
            const float4* ap = (const float4*)(g_actS + (b * DD + d) * AA);
            float4 a0 = ap[0], a1 = ap[1], a2 = ap[2], a3 = ap[3];
            ar[0]=a0.x; ar[1]=a0.y; ar[2]=a0.z; ar[3]=a0.w;
            ar[4]=a1.x; ar[5]=a1.y; ar[6]=a1.z; ar[7]=a1.w;
            ar[8]=a2.x; ar[9]=a2.y; ar[10]=a2.z; ar[11]=a2.w;
            ar[12]=a3.x; ar[13]=a3.y; ar[14]=a3.z; ar[15]=a3.w;
        }

        float acc[16];
#pragma unroll
        for (int a = 0; a < 16; a++) acc[a] = 0.f;

        int i = ilo;
        for (; i + 2 <= ihi; i += 2) {
            const uint4* vp0 = (const uint4*)(g_votes + ((size_t)i * BB + b) * OO + d * 16);
            const uint4* vp1 = (const uint4*)(g_votes + ((size_t)(i + 1) * BB + b) * OO + d * 16);
            uint4 p0 = vp0[0], p1 = vp0[1];
            uint4 q0 = vp1[0], q1 = vp1[1];

            float v0[16], v1[16];
            {
                const __half2* h;
                h = (const __half2*)&p0;
#pragma unroll
                for (int j = 0; j < 4; j++) { float2 f = __half22float2(h[j]); v0[2*j]=f.x; v0[2*j+1]=f.y; }
                h = (const __half2*)&p1;
#pragma unroll
                for (int j = 0; j < 4; j++) { float2 f = __half22float2(h[j]); v0[8+2*j]=f.x; v0[8+2*j+1]=f.y; }
                h = (const __half2*)&q0;
#pragma unroll
                for (int j = 0; j < 4; j++) { float2 f = __half22float2(h[j]); v1[2*j]=f.x; v1[2*j+1]=f.y; }
                h = (const __half2*)&q1;
#pragma unroll
                for (int j = 0; j < 4; j++) { float2 f = __half22float2(h[j]); v1[8+2*j]=f.x; v1[8+2*j+1]=f.y; }
            }

            float u0 = 0.f, u1 = 0.f;
#pragma unroll
            for (int a = 0; a < 16; a++) { u0 = fmaf(v0[a], ar[a], u0); u1 = fmaf(v1[a], ar[a], u1); }

            float e0 = __expf(u0), e1 = __expf(u1);
            float s0 = e0, s1 = e1;
#pragma unroll
            for (int o = 16; o >= 1; o >>= 1) {
                s0 += __shfl_xor_sync(0xffffffffu, s0, o);
                s1 += __shfl_xor_sync(0xffffffffu, s1, o);
            }
            const float r0 = __fdividef(e0, s0);
            const float r1 = __fdividef(e1, s1);
#pragma unroll
            for (int a = 0; a < 16; a++) acc[a] = fmaf(r0, v0[a], fmaf(r1, v1[a], acc[a]));
        }
        if (i < ihi) {
            const uint4* vp = (const uint4*)(g_votes + ((size_t)i * BB + b) * OO + d * 16);
            uint4 p0 = vp[0], p1 = vp[1];
            float v[16];
            {
                const __half2* h0 = (const __half2*)&p0;
                const __half2* h1 = (const __half2*)&p1;
#pragma unroll
                for (int j = 0; j < 4; j++) {
                    float2 f = __half22float2(h0[j]); v[2*j]=f.x; v[2*j+1]=f.y;
                    float2 g = __half22float2(h1[j]); v[8+2*j]=g.x; v[8+2*j+1]=g.y;
                }
            }
            float u = 0.f;
#pragma unroll
            for (int a = 0; a < 16; a++) u = fmaf(v[a], ar[a], u);
            float e = __expf(u), s = e;
#pragma unroll
            for (int o = 16; o >= 1; o >>= 1) s += __shfl_xor_sync(0xffffffffu, s, o);
            const float r = __fdividef(e, s);
#pragma unroll
            for (int a = 0; a < 16; a++) acc[a] = fmaf(r, v[a], acc[a]);
        }

        float* dst = g_part + (size_t)bx * BO + (b * DD + d) * AA;
        float4* d4 = (float4*)dst;
        d4[0] = make_float4(acc[0], acc[1], acc[2], acc[3]);
        d4[1] = make_float4(acc[4], acc[5], acc[6], acc[7]);
        d4[2] = make_float4(acc[8], acc[9], acc[10], acc[11]);
        d4[3] = make_float4(acc[12], acc[13], acc[14], acc[15]);
    }
}

// ---------------------------------------------------------------------------
// Fused persistent kernel: votes -> squash0 -> route1 -> squash1 -> route2
// -> squash2, with software grid barriers between phases.
// ---------------------------------------------------------------------------
__global__ __launch_bounds__(NT, 1) void caps_kernel(const float* __restrict__ x,
                                                     const float* __restrict__ w,
                                                     const float* __restrict__ bias,
                                                     float* __restrict__ out) {
    extern __shared__ __align__(16) char smem[];

    // ================= Phase 1: votes =================
    {
        float4* swbuf = (float4*)smem;                   // [2][2048] float4
        float*  sxbuf = (float*)(smem + 2 * 32768);      // [2][512] float

        const int t    = threadIdx.x;
        const int lane = t & 31;
        const int wid  = t >> 5;
        const int half = wid >> 3;       // o-half (0..1)
        const int bg   = wid & 7;        // b-group (4 b's each)
        const int bx   = blockIdx.x;
        const int n    = (II - bx + NB - 1) / NB;

        const int q0   = half * 64 + lane * 2;
        const int idx0 = swz(q0);
        const int idx1 = idx0 ^ 1;
        const int obase = half * 256 + lane * 8;

        ull sacc[4][4];
#pragma unroll
        for (int j = 0; j < 4; j++)
#pragma unroll
            for (int k = 0; k < 4; k++) sacc[j][k] = 0ull;

        // prefetch iteration 0
        {
            const float4* wsrc = (const float4*)(w + (size_t)bx * CC * OO);
#pragma unroll
            for (int kk = 0; kk < 4; kk++) {
                int g = t + 512 * kk;
                int c = g >> 7, q = g & 127;
                cpa16(&swbuf[c * 128 + swz(q)], wsrc + g);
            }
            if (t < 128) {
                int b = t >> 2, p = t & 3;
                cpa16((float4*)sxbuf + t, (const float4*)(x + ((size_t)b * II + bx) * CC) + p);
            }
        }
        CP_COMMIT();

        for (int it = 0; it < n; it++) {
            const int i = bx + it * NB;
            const bool hn = (it + 1) < n;
            if (hn) {
                const int i2 = bx + (it + 1) * NB;
                const int buf = (it + 1) & 1;
                const float4* wsrc = (const float4*)(w + (size_t)i2 * CC * OO);
                float4* wd = swbuf + buf * WBUF_F4;
#pragma unroll
                for (int kk = 0; kk < 4; kk++) {
                    int g = t + 512 * kk;
                    int c = g >> 7, q = g & 127;
                    cpa16(&wd[c * 128 + swz(q)], wsrc + g);
                }
                if (t < 128) {
                    int b = t >> 2, p = t & 3;
                    cpa16((float4*)(sxbuf + buf * 512) + t,
                          (const float4*)(x + ((size_t)b * II + i2) * CC) + p);
                }
            }
            CP_COMMIT();
            if (hn) { CP_WAIT(1); } else { CP_WAIT(0); }
            __syncthreads();

            const float4* sw4 = swbuf + (it & 1) * WBUF_F4;
            const float*  sxp = sxbuf + (it & 1) * 512;

            ull acc[4][4];
#pragma unroll
            for (int j = 0; j < 4; j++)
#pragma unroll
                for (int k = 0; k < 4; k++) acc[j][k] = 0ull;

#pragma unroll
            for (int c = 0; c < CC; c++) {
                const float4 wa = sw4[c * 128 + idx0];
                const float4 wb = sw4[c * 128 + idx1];
                ull wv[4];
                wv[0] = pack2(wa.x, wa.y); wv[1] = pack2(wa.z, wa.w);
                wv[2] = pack2(wb.x, wb.y); wv[3] = pack2(wb.z, wb.w);
#pragma unroll
                for (int bb = 0; bb < 4; bb++) {
                    const float xs = sxp[(bg * 4 + bb) * CC + c];   // warp-uniform broadcast
                    const ull xx = pack2(xs, xs);
#pragma unroll
                    for (int k = 0; k < 4; k++) fma2(acc[bb][k], xx, wv[k]);
                }
            }

            // store fp16 votes + accumulate iter0 partials
#pragma unroll
            for (int bb = 0; bb < 4; bb++) {
                const int b = bg * 4 + bb;
                __half2 h[4];
#pragma unroll
                for (int k = 0; k < 4; k++) {
                    float lo, hi; unpack2(acc[bb][k], lo, hi);
                    h[k] = __floats2half2_rn(lo, hi);
                    add2(sacc[bb][k], acc[bb][k]);
                }
                *(uint4*)(g_votes + ((size_t)i * BB + b) * OO + obase) = *(uint4*)h;
            }
            __syncthreads();   // compute done before this buffer is refilled
        }

        // deterministic per-block partial write (row = blockIdx.x)
#pragma unroll
        for (int bb = 0; bb < 4; bb++) {
            const int b = bg * 4 + bb;
            float* dst = g_part + (size_t)bx * BO + b * OO + obase;
#pragma unroll
            for (int k = 0; k < 4; k++) {
                float lo, hi; unpack2(sacc[bb][k], lo, hi);
                dst[2 * k] = lo; dst[2 * k + 1] = hi;
            }
        }
    }

    grid_sync();
    squash_phase(1.0f / 32.0f, (const float*)bias, g_actS, 0);  // actS = act0
    grid_sync();
    route_phase();                                              // softmax(u(act0))
    grid_sync();
    squash_phase(1.0f, bias, g_actS, 1);                        // actS = act0 + act1
    grid_sync();
    route_phase();                                              // softmax(u(act0+act1))
    grid_sync();
    squash_phase(1.0f, bias, out, 0);                           // final activation
}

// ---------------------------------------------------------------------------
extern "C" void kernel_launch(void* const* d_in, const int* in_sizes, int n_in,
                              void* d_out, int out_size) {
    const float* x    = (const float*)d_in[0];
    const float* w    = (const float*)d_in[1];
    const float* bias = (const float*)d_in[2];
    float* out = (float*)d_out;

    cudaFuncSetAttribute(caps_kernel, cudaFuncAttributeMaxDynamicSharedMemorySize, SMEM_TOTAL);
    caps_kernel<<<NB, NT, SMEM_TOTAL>>>(x, w, bias, out);
}

// round 5
// speedup vs baseline: 2.2667x; 1.0257x over previous
#include <cuda_runtime.h>
#include <cuda_fp16.h>
#include <cstdint>

// Problem constants (fixed by the dataset)
#define BB 32      // batch
#define II 2048    // input capsules
#define CC 16      // input atoms (contraction dim)
#define DD 32      // output capsules
#define AA 16      // output atoms
#define OO 512     // DD*AA
#define BO (BB*OO) // 16384
#define NB 148     // persistent blocks = one per SM
#define NT 1024    // 32 warps -> occ 50%

typedef unsigned long long ull;

// Scratch (static __device__ arrays: no dynamic allocation)
__device__ __half g_votes[(size_t)II * BB * OO];     // [i][b][o] fp16, 67 MB (L2-resident)
__device__ float  g_part[(size_t)NB * BO];           // per-block partials, 9.7 MB
__device__ float  g_actS[BO];                        // act0, then act0+act1
__device__ unsigned g_count;                          // barrier arrive counter (self-resetting)
__device__ volatile unsigned g_sense;                 // barrier generation (monotonic)

// ---------------- packed f32x2 helpers ----------------
__device__ __forceinline__ ull pack2(float lo, float hi) {
    ull r; asm("mov.b64 %0, {%1,%2};" : "=l"(r) : "f"(lo), "f"(hi)); return r;
}
__device__ __forceinline__ void unpack2(ull v, float& lo, float& hi) {
    asm("mov.b64 {%0,%1}, %2;" : "=f"(lo), "=f"(hi) : "l"(v));
}
__device__ __forceinline__ void fma2(ull& d, ull a, ull b) {
    asm("fma.rn.f32x2 %0, %1, %2, %0;" : "+l"(d) : "l"(a), "l"(b));
}
__device__ __forceinline__ void add2(ull& d, ull a) {
    asm("add.rn.f32x2 %0, %1, %0;" : "+l"(d) : "l"(a));
}

// ---------------- cp.async helpers ----------------
__device__ __forceinline__ void cpa16(void* dst, const void* src) {
    unsigned sdst = (unsigned)__cvta_generic_to_shared(dst);
    asm volatile("cp.async.cg.shared.global [%0], [%1], 16;\n" :: "r"(sdst), "l"(src));
}
#define CP_COMMIT() asm volatile("cp.async.commit_group;\n")
#define CP_WAIT(N)  asm volatile("cp.async.wait_group %0;\n" :: "n"(N))

#define WBUF_F4 2048                       // float4s per W buffer (32 KB)
#define SMEM_TOTAL (2*32768 + 2*2048)      // 2 W buffers + 2 x buffers = 69632 B

// ---------------------------------------------------------------------------
// Software grid barrier (sense-reversing). 148 blocks co-resident (1/SM).
// ---------------------------------------------------------------------------
__device__ __forceinline__ void grid_sync() {
    __syncthreads();
    if (threadIdx.x == 0) {
        unsigned gen = g_sense;
        __threadfence();
        if (atomicAdd(&g_count, 1u) == NB - 1) {
            g_count = 0;
            __threadfence();
            g_sense = gen + 1;
        } else {
            while (g_sense == gen) __nanosleep(32);
        }
        __threadfence();
    }
    __syncthreads();
}

// ---------------------------------------------------------------------------
// Squash phase: blocks 0..31 (b = blockIdx.x). 1024 threads:
//   thread = (ks 0..7, o4 0..127): float4 partial sums over rows ks, ks+8, ...
//   smem tree (fixed order, deterministic), then 128 threads finalize.
// smem red[] aliases the votes W buffers (dead by now; grid_sync bars order).
// ---------------------------------------------------------------------------
__device__ __forceinline__ void squash_phase(char* smem, float scale,
                                             const float* __restrict__ bias,
                                             float* __restrict__ dst, int accumulate) {
    if (blockIdx.x < BB) {
        float4* red = (float4*)smem;                 // [8][128] float4 = 16 KB
        const int b  = blockIdx.x;
        const int ks = threadIdx.x >> 7;
        const int o4 = threadIdx.x & 127;
        const float4* gp = (const float4*)g_part;
        const int col = b * 128 + o4;                // float4 column index

        float4 s = make_float4(0.f, 0.f, 0.f, 0.f);
        for (int k = ks; k < NB; k += 8) {
            float4 v = gp[(size_t)k * (BO / 4) + col];
            s.x += v.x; s.y += v.y; s.z += v.z; s.w += v.w;
        }
        red[ks * 128 + o4] = s;
        __syncthreads();

        if (threadIdx.x < 128) {
            const int t = threadIdx.x;
            float4 r0 = red[t],        r1 = red[128 + t];
            float4 r2 = red[256 + t],  r3 = red[384 + t];
            float4 r4 = red[512 + t],  r5 = red[640 + t];
            float4 r6 = red[768 + t],  r7 = red[896 + t];
            float4 sum;
            sum.x = ((r0.x + r1.x) + (r2.x + r3.x)) + ((r4.x + r5.x) + (r6.x + r7.x));
            sum.y = ((r0.y + r1.y) + (r2.y + r3.y)) + ((r4.y + r5.y) + (r6.y + r7.y));
            sum.z = ((r0.z + r1.z) + (r2.z + r3.z)) + ((r4.z + r5.z) + (r6.z + r7.z));
            sum.w = ((r0.w + r1.w) + (r2.w + r3.w)) + ((r4.w + r5.w) + (r6.w + r7.w));

            const float4 bi = ((const float4*)bias)[t];
            float4 val;
            val.x = fmaf(sum.x, scale, bi.x);
            val.y = fmaf(sum.y, scale, bi.y);
            val.z = fmaf(sum.z, scale, bi.z);
            val.w = fmaf(sum.w, scale, bi.w);

            // atom group = 16 o = 4 consecutive o4-threads (aligned in lane groups of 4)
            float n2 = (val.x * val.x + val.y * val.y) + (val.z * val.z + val.w * val.w);
            n2 += __shfl_xor_sync(0xffffffffu, n2, 1);
            n2 += __shfl_xor_sync(0xffffffffu, n2, 2);
            const float f = sqrtf(n2) / (1.f + n2);

            float4* dp = (float4*)dst + b * 128 + t;
            if (accumulate) {
                float4 cur = *dp;
                cur.x = fmaf(val.x, f, cur.x); cur.y = fmaf(val.y, f, cur.y);
                cur.z = fmaf(val.z, f, cur.z); cur.w = fmaf(val.w, f, cur.w);
                *dp = cur;
            } else {
                *dp = make_float4(val.x * f, val.y * f, val.z * f, val.w * f);
            }
        }
    }
    __syncthreads();
}

// ---------------------------------------------------------------------------
// Route phase: block bx owns i in [ilo, ihi); warp = one b (32 warps = 32 b);
// lane = one d. Per i: load 2x LDG.128 (L2-resident), dot, warp softmax over
// d, weighted accumulate. Writes partial preact row bx (fixed order).
// ---------------------------------------------------------------------------
__device__ __forceinline__ void route_phase() {
    const int b    = threadIdx.x >> 5;
    const int lane = threadIdx.x & 31;
    const int bx   = blockIdx.x;
    const int ilo  = (bx * II) / NB;
    const int ihi  = ((bx + 1) * II) / NB;
    const int d    = lane;

    float ar[16];
    {
        const float4* ap = (const float4*)(g_actS + (b * DD + d) * AA);
        float4 a0 = ap[0], a1 = ap[1], a2 = ap[2], a3 = ap[3];
        ar[0]=a0.x; ar[1]=a0.y; ar[2]=a0.z; ar[3]=a0.w;
        ar[4]=a1.x; ar[5]=a1.y; ar[6]=a1.z; ar[7]=a1.w;
        ar[8]=a2.x; ar[9]=a2.y; ar[10]=a2.z; ar[11]=a2.w;
        ar[12]=a3.x; ar[13]=a3.y; ar[14]=a3.z; ar[15]=a3.w;
    }

    float acc[16];
#pragma unroll
    for (int a = 0; a < 16; a++) acc[a] = 0.f;

    const __half* vbase = g_votes + (size_t)b * OO + d * 16;
    for (int i = ilo; i < ihi; i++) {
        const uint4* vp = (const uint4*)(vbase + (size_t)i * (BB * OO));
        uint4 p0 = vp[0], p1 = vp[1];

        float v[16];
        {
            const __half2* h0 = (const __half2*)&p0;
            const __half2* h1 = (const __half2*)&p1;
#pragma unroll
            for (int j = 0; j < 4; j++) {
                float2 f = __half22float2(h0[j]); v[2*j]   = f.x; v[2*j+1]   = f.y;
                float2 g = __half22float2(h1[j]); v[8+2*j] = g.x; v[8+2*j+1] = g.y;
            }
        }
        float u = 0.f;
#pragma unroll
        for (int a = 0; a < 16; a++) u = fmaf(v[a], ar[a], u);

        // softmax over d (32 lanes); |u| small enough to skip max-subtract
        float e = __expf(u);
        float s = e;
#pragma unroll
        for (int o = 16; o >= 1; o >>= 1) s += __shfl_xor_sync(0xffffffffu, s, o);
        const float r = __fdividef(e, s);
#pragma unroll
        for (int a = 0; a < 16; a++) acc[a] = fmaf(r, v[a], acc[a]);
    }

    float4* d4 = (float4*)(g_part + (size_t)bx * BO + (b * DD + d) * AA);
    d4[0] = make_float4(acc[0], acc[1], acc[2], acc[3]);
    d4[1] = make_float4(acc[4], acc[5], acc[6], acc[7]);
    d4[2] = make_float4(acc[8], acc[9], acc[10], acc[11]);
    d4[3] = make_float4(acc[12], acc[13], acc[14], acc[15]);
}

// ---------------------------------------------------------------------------
// Fused persistent kernel: votes -> squash0 -> route1 -> squash1 -> route2
// -> squash2, with software grid barriers between phases.
// ---------------------------------------------------------------------------
__global__ __launch_bounds__(NT, 1) void caps_kernel(const float* __restrict__ x,
                                                     const float* __restrict__ w,
                                                     const float* __restrict__ bias,
                                                     float* __restrict__ out) {
    extern __shared__ __align__(16) char smem[];

    // ================= Phase 1: votes =================
    // 32 warps = 4 o-quarters x 8 b-groups(4 b). lane owns 4 consecutive o.
    // W tile read: 1 LDS.128 per c at q = c*128 + oq*32 + lane (32 consecutive
    // float4s per warp -> conflict-free, no swizzle). cp.async double-buffered.
    {
        float4* swbuf = (float4*)smem;                   // [2][2048] float4
        float*  sxbuf = (float*)(smem + 2 * 32768);      // [2][512] float

        const int t    = threadIdx.x;
        const int lane = t & 31;
        const int wid  = t >> 5;
        const int oq   = wid >> 3;       // o-quarter (0..3)
        const int bg   = wid & 7;        // b-group (4 b each)
        const int bx   = blockIdx.x;
        const int n    = (II - bx + NB - 1) / NB;
        const int qidx = oq * 32 + lane;            // float4 index within a c-row
        const int obase = oq * 128 + lane * 4;

        ull sacc[4][2];
#pragma unroll
        for (int j = 0; j < 4; j++) { sacc[j][0] = 0ull; sacc[j][1] = 0ull; }

        // prefetch iteration 0
        {
            const float4* wsrc = (const float4*)(w + (size_t)bx * CC * OO);
            cpa16(&swbuf[t],        wsrc + t);
            cpa16(&swbuf[t + 1024], wsrc + t + 1024);
            if (t < 128) {
                int b = t >> 2, p = t & 3;
                cpa16((float4*)sxbuf + t, (const float4*)(x + ((size_t)b * II + bx) * CC) + p);
            }
        }
        CP_COMMIT();

        for (int it = 0; it < n; it++) {
            const int i = bx + it * NB;
            const bool hn = (it + 1) < n;
            if (hn) {
                const int i2 = bx + (it + 1) * NB;
                const int buf = (it + 1) & 1;
                const float4* wsrc = (const float4*)(w + (size_t)i2 * CC * OO);
                float4* wd = swbuf + buf * WBUF_F4;
                cpa16(&wd[t],        wsrc + t);
                cpa16(&wd[t + 1024], wsrc + t + 1024);
                if (t < 128) {
                    int b = t >> 2, p = t & 3;
                    cpa16((float4*)(sxbuf + buf * 512) + t,
                          (const float4*)(x + ((size_t)b * II + i2) * CC) + p);
                }
            }
            CP_COMMIT();
            if (hn) { CP_WAIT(1); } else { CP_WAIT(0); }
            __syncthreads();

            const float4* sw4 = swbuf + (it & 1) * WBUF_F4;
            const float*  sxp = sxbuf + (it & 1) * 512;

            ull acc[4][2];
#pragma unroll
            for (int j = 0; j < 4; j++) { acc[j][0] = 0ull; acc[j][1] = 0ull; }

#pragma unroll
            for (int c = 0; c < CC; c++) {
                const float4 wa = sw4[c * 128 + qidx];
                const ull wv0 = pack2(wa.x, wa.y);
                const ull wv1 = pack2(wa.z, wa.w);
#pragma unroll
                for (int bb = 0; bb < 4; bb++) {
                    const float xs = sxp[(bg * 4 + bb) * CC + c];   // warp-uniform broadcast
                    const ull xx = pack2(xs, xs);
                    fma2(acc[bb][0], xx, wv0);
                    fma2(acc[bb][1], xx, wv1);
                }
            }

            // store fp16 votes (STG.64, 256 B coalesced per warp) + iter0 partials
#pragma unroll
            for (int bb = 0; bb < 4; bb++) {
                const int b = bg * 4 + bb;
                float l0, h0, l1, h1;
                unpack2(acc[bb][0], l0, h0);
                unpack2(acc[bb][1], l1, h1);
                __half2 hh[2] = { __floats2half2_rn(l0, h0), __floats2half2_rn(l1, h1) };
                *(uint2*)(g_votes + ((size_t)i * BB + b) * OO + obase) = *(uint2*)hh;
                add2(sacc[bb][0], acc[bb][0]);
                add2(sacc[bb][1], acc[bb][1]);
            }
            __syncthreads();   // compute done before this buffer is refilled
        }

        // deterministic per-block partial write (row = blockIdx.x)
#pragma unroll
        for (int bb = 0; bb < 4; bb++) {
            const int b = bg * 4 + bb;
            float l0, h0, l1, h1;
            unpack2(sacc[bb][0], l0, h0);
            unpack2(sacc[bb][1], l1, h1);
            *(float4*)(g_part + (size_t)bx * BO + b * OO + obase) = make_float4(l0, h0, l1, h1);
        }
    }

    grid_sync();
    squash_phase(smem, 1.0f / 32.0f, bias, g_actS, 0);  // actS = act0
    grid_sync();
    route_phase();                                      // softmax(u(act0))
    grid_sync();
    squash_phase(smem, 1.0f, bias, g_actS, 1);          // actS = act0 + act1
    grid_sync();
    route_phase();                                      // softmax(u(act0+act1))
    grid_sync();
    squash_phase(smem, 1.0f, bias, out, 0);             // final activation
}

// ---------------------------------------------------------------------------
extern "C" void kernel_launch(void* const* d_in, const int* in_sizes, int n_in,
                              void* d_out, int out_size) {
    const float* x    = (const float*)d_in[0];
    const float* w    = (const float*)d_in[1];
    const float* bias = (const float*)d_in[2];
    float* out = (float*)d_out;

    cudaFuncSetAttribute(caps_kernel, cudaFuncAttributeMaxDynamicSharedMemorySize, SMEM_TOTAL);
    caps_kernel<<<NB, NT, SMEM_TOTAL>>>(x, w, bias, out);
}